// round 9
// baseline (speedup 1.0000x reference)
#include <cuda_runtime.h>
#include <cuda_bf16.h>
#include <cuda_fp8.h>
#include <cstdint>
#include <math.h>

// Problem constants
#define BD 64                 // batch
#define NP 576                // patches per image (24*24)
#define DD 768                // hidden = 3*16*16
#define LL 1024               // latents
#define MROWS (BD * NP)       // 36864 flattened (b, patch) rows

#define FP8_SCALE 8.0f        // operand scale before e4m3 quantization
#define EXP_COEF 0.03125f     // 2 / (FP8_SCALE*FP8_SCALE) : exp(2*sim)=exp(acc*this)

// ---------------------------------------------------------------------------
// Scratch (__device__ globals: allocation-free per harness rules)
// ---------------------------------------------------------------------------
__device__ __align__(16) float         g_patch[(size_t)MROWS * DD]; // conv out fp32
__device__ __align__(16) __nv_bfloat16 g_xim [(size_t)MROWS * DD];  // im2col(x) bf16
__device__ __align__(16) __nv_bfloat16 g_wb  [(size_t)DD * DD];     // conv weights bf16
__device__ __align__(16) unsigned char g_pn8 [(size_t)MROWS * DD];  // normalized patches e4m3*8
__device__ __align__(16) unsigned char g_ln8 [(size_t)LL * DD];     // normalized latent  e4m3*8
__device__ float g_far[BD];
__device__ float g_close[BD];

// ---------------------------------------------------------------------------
// Helpers
// ---------------------------------------------------------------------------
__device__ __forceinline__ uint32_t smem_to_u32(const void* smem_ptr) {
    uint32_t addr;
    asm("{ .reg .u64 tmp; cvta.to.shared.u64 tmp, %1; cvt.u32.u64 %0, tmp; }"
        : "=r"(addr) : "l"(smem_ptr));
    return addr;
}

__device__ __forceinline__ float warpSum(float v) {
#pragma unroll
    for (int o = 16; o; o >>= 1) v += __shfl_xor_sync(0xffffffffu, v, o);
    return v;
}

__device__ __forceinline__ void ldsm_x4(uint32_t* d, uint32_t addr) {
    asm volatile("ldmatrix.sync.aligned.m8n8.x4.shared.b16 {%0,%1,%2,%3}, [%4];"
                 : "=r"(d[0]), "=r"(d[1]), "=r"(d[2]), "=r"(d[3]) : "r"(addr));
}

__device__ __forceinline__ void mma_bf16(float* c, const uint32_t* a,
                                         uint32_t b0, uint32_t b1) {
    asm volatile(
        "mma.sync.aligned.m16n8k16.row.col.f32.bf16.bf16.f32 "
        "{%0,%1,%2,%3}, {%4,%5,%6,%7}, {%8,%9}, {%0,%1,%2,%3};"
        : "+f"(c[0]), "+f"(c[1]), "+f"(c[2]), "+f"(c[3])
        : "r"(a[0]), "r"(a[1]), "r"(a[2]), "r"(a[3]), "r"(b0), "r"(b1));
}

__device__ __forceinline__ void mma_fp8(float* c, const uint32_t* a,
                                        uint32_t b0, uint32_t b1) {
    asm volatile(
        "mma.sync.aligned.m16n8k32.row.col.f32.e4m3.e4m3.f32 "
        "{%0,%1,%2,%3}, {%4,%5,%6,%7}, {%8,%9}, {%0,%1,%2,%3};"
        : "+f"(c[0]), "+f"(c[1]), "+f"(c[2]), "+f"(c[3])
        : "r"(a[0]), "r"(a[1]), "r"(a[2]), "r"(a[3]), "r"(b0), "r"(b1));
}

__device__ __forceinline__ void cp16(uint32_t saddr, const void* gptr) {
    asm volatile("cp.async.cg.shared.global [%0], [%1], 16;" :: "r"(saddr), "l"(gptr));
}

#define CP_COMMIT() asm volatile("cp.async.commit_group;")

#define SWZ(off) ((off) ^ (((off) >> 3) & 0x70))

// ---------------------------------------------------------------------------
// Pre-pass kernels
// ---------------------------------------------------------------------------

// im2col + fp32->bf16: g_xim[(b*576+np)*768 + k], k = c*256 + rr*16 + cc
__global__ __launch_bounds__(256) void im2col_kernel(const float* __restrict__ x) {
    int s = blockIdx.x * 256 + threadIdx.x;
    int row = s / 48;
    int seg = s - row * 48;
    int b   = row / NP;
    int np  = row - b * NP;
    int ph  = np / 24, pw = np - ph * 24;
    int c   = seg >> 4, rr = seg & 15;
    const float4* src = (const float4*)(x + ((size_t)(b * 3 + c) * 384 + ph * 16 + rr) * 384 + pw * 16);
    float4 q0 = src[0], q1 = src[1], q2 = src[2], q3 = src[3];
    __align__(16) __nv_bfloat162 h[8];
    h[0] = __floats2bfloat162_rn(q0.x, q0.y); h[1] = __floats2bfloat162_rn(q0.z, q0.w);
    h[2] = __floats2bfloat162_rn(q1.x, q1.y); h[3] = __floats2bfloat162_rn(q1.z, q1.w);
    h[4] = __floats2bfloat162_rn(q2.x, q2.y); h[5] = __floats2bfloat162_rn(q2.z, q2.w);
    h[6] = __floats2bfloat162_rn(q3.x, q3.y); h[7] = __floats2bfloat162_rn(q3.z, q3.w);
    uint4* dst = (uint4*)(g_xim + (size_t)row * DD + seg * 16);
    dst[0] = ((const uint4*)h)[0];
    dst[1] = ((const uint4*)h)[1];
}

// conv weights fp32 -> bf16 (OIHW flattening == k order)
__global__ __launch_bounds__(256) void wconv_kernel(const float* __restrict__ w) {
    int i = blockIdx.x * 256 + threadIdx.x;   // 147456 float4s
    float4 q = ((const float4*)w)[i];
    __align__(8) __nv_bfloat162 h2[2] = {__floats2bfloat162_rn(q.x, q.y),
                                         __floats2bfloat162_rn(q.z, q.w)};
    ((uint2*)g_wb)[i] = *(const uint2*)h2;
}

// L2-normalize conv output rows -> scaled e4m3. grid = MROWS, 256 thr.
__global__ __launch_bounds__(256) void norm_patch_kernel() {
    const float* p = g_patch + (size_t)blockIdx.x * DD;
    unsigned char* o = g_pn8 + (size_t)blockIdx.x * DD;
    const int tid = threadIdx.x;
    float v0 = p[tid], v1 = p[tid + 256], v2 = p[tid + 512];
    float ss = v0 * v0 + v1 * v1 + v2 * v2;

    __shared__ float red[8];
    __shared__ float s_inv;
    float t = warpSum(ss);
    if ((tid & 31) == 0) red[tid >> 5] = t;
    __syncthreads();
    if (tid < 32) {
        float u = (tid < 8) ? red[tid] : 0.f;
        u = warpSum(u);
        if (tid == 0) s_inv = FP8_SCALE / fmaxf(sqrtf(u), 1e-8f);
    }
    __syncthreads();
    const float inv = s_inv;
    o[tid]       = (unsigned char)__nv_cvt_float_to_fp8(v0 * inv, __NV_SATFINITE, __NV_E4M3);
    o[tid + 256] = (unsigned char)__nv_cvt_float_to_fp8(v1 * inv, __NV_SATFINITE, __NV_E4M3);
    o[tid + 512] = (unsigned char)__nv_cvt_float_to_fp8(v2 * inv, __NV_SATFINITE, __NV_E4M3);
}

// Normalize latent rows -> scaled e4m3. grid = LL, 256 thr.
__global__ __launch_bounds__(256) void norm_latent_kernel(const float* __restrict__ latent) {
    const float* s = latent + (size_t)blockIdx.x * DD;
    unsigned char* d = g_ln8 + (size_t)blockIdx.x * DD;
    const int tid = threadIdx.x;
    float v0 = s[tid], v1 = s[tid + 256], v2 = s[tid + 512];
    float ss = v0 * v0 + v1 * v1 + v2 * v2;

    __shared__ float red[8];
    __shared__ float s_inv;
    float t = warpSum(ss);
    if ((tid & 31) == 0) red[tid >> 5] = t;
    __syncthreads();
    if (tid < 32) {
        float u = (tid < 8) ? red[tid] : 0.f;
        u = warpSum(u);
        if (tid == 0) s_inv = FP8_SCALE / fmaxf(sqrtf(u), 1e-8f);
    }
    __syncthreads();
    const float inv = s_inv;
    d[tid]       = (unsigned char)__nv_cvt_float_to_fp8(v0 * inv, __NV_SATFINITE, __NV_E4M3);
    d[tid + 256] = (unsigned char)__nv_cvt_float_to_fp8(v1 * inv, __NV_SATFINITE, __NV_E4M3);
    d[tid + 512] = (unsigned char)__nv_cvt_float_to_fp8(v2 * inv, __NV_SATFINITE, __NV_E4M3);
}

// ---------------------------------------------------------------------------
// Conv GEMM (bf16, R6-proven 2-stage): 128x128 tile, BK=64, cp.async double
// buffer, SW128 swizzle + ldmatrix, mma m16n8k16, bias-add epilogue.
// Warp layout: 8 warps = 4 (m) x 2 (n); warp tile 32(m) x 64(n).
// ---------------------------------------------------------------------------
#define NCHUNK 12
#define TILE_B 16384
#define SMEM_DYN (4 * TILE_B)

__global__ __launch_bounds__(256)
void conv_mma_kernel(const float* __restrict__ bias) {
    extern __shared__ __align__(1024) unsigned char smem[];
    const uint32_t sbase = smem_to_u32(smem);
    const int tid = threadIdx.x, lane = tid & 31, wid = tid >> 5;
    const int warp_m = wid & 3, warp_n = wid >> 2;

    const int m0 = blockIdx.x * 128, n0 = blockIdx.y * 128;
    const __nv_bfloat16* Ap = g_xim;
    const __nv_bfloat16* Bp = g_wb;

    const __nv_bfloat16* gA[4];
    const __nv_bfloat16* gB[4];
    uint32_t swoff[4];
#pragma unroll
    for (int i = 0; i < 4; ++i) {
        int idx = tid + i * 256;
        int rr = idx >> 3, cc = idx & 7;
        swoff[i] = SWZ((uint32_t)(rr * 128 + cc * 16));
        gA[i] = Ap + (size_t)(m0 + rr) * DD + cc * 8;
        gB[i] = Bp + (size_t)(n0 + rr) * DD + cc * 8;
    }

#define LOAD_CHUNK(ch, buf) do {                                        \
        uint32_t _sA = sbase + (uint32_t)(buf) * (2 * TILE_B);          \
        uint32_t _sB = _sA + TILE_B;                                    \
        _Pragma("unroll")                                               \
        for (int i = 0; i < 4; ++i) {                                   \
            cp16(_sA + swoff[i], (const void*)(gA[i] + (ch) * 64));     \
            cp16(_sB + swoff[i], (const void*)(gB[i] + (ch) * 64));     \
        }                                                               \
        CP_COMMIT();                                                    \
    } while (0)

    float acc[2][8][4] = {};

    const int arow = warp_m * 32 + (lane & 15);
    const int ac16 = lane >> 4;
    const int brow = warp_n * 64 + (lane & 7) + ((lane >> 4) << 3);
    const int bc16 = (lane >> 3) & 1;

    LOAD_CHUNK(0, 0);

    for (int ch = 0; ch < NCHUNK; ++ch) {
        const int buf = ch & 1;
        if (ch < NCHUNK - 1) {
            LOAD_CHUNK(ch + 1, buf ^ 1);
            asm volatile("cp.async.wait_group 1;");
        } else {
            asm volatile("cp.async.wait_group 0;");
        }
        __syncthreads();

        const uint32_t aT = sbase + (uint32_t)buf * (2 * TILE_B);
        const uint32_t bT = aT + TILE_B;
#pragma unroll
        for (int kk = 0; kk < 4; ++kk) {
            uint32_t af[2][4];
#pragma unroll
            for (int mt = 0; mt < 2; ++mt) {
                uint32_t off = (uint32_t)((arow + mt * 16) * 128 + (kk * 2 + ac16) * 16);
                ldsm_x4(af[mt], aT + SWZ(off));
            }
#pragma unroll
            for (int nt = 0; nt < 4; ++nt) {
                uint32_t bf4[4];
                uint32_t off = (uint32_t)((brow + nt * 16) * 128 + (kk * 2 + bc16) * 16);
                ldsm_x4(bf4, bT + SWZ(off));
#pragma unroll
                for (int mt = 0; mt < 2; ++mt) {
                    mma_bf16(acc[mt][nt * 2 + 0], af[mt], bf4[0], bf4[1]);
                    mma_bf16(acc[mt][nt * 2 + 1], af[mt], bf4[2], bf4[3]);
                }
            }
        }
        __syncthreads();
    }
#undef LOAD_CHUNK

    const int mrow_lo = warp_m * 32 + (lane >> 2);
    const int ncol0   = warp_n * 64 + (lane & 3) * 2;
#pragma unroll
    for (int mt = 0; mt < 2; ++mt) {
#pragma unroll
        for (int nt = 0; nt < 8; ++nt) {
            int m_a = m0 + mrow_lo + mt * 16;
            int nn  = n0 + ncol0 + nt * 8;
            float2 b2 = *(const float2*)(bias + nn);
            float2 o0 = {acc[mt][nt][0] + b2.x, acc[mt][nt][1] + b2.y};
            float2 o1 = {acc[mt][nt][2] + b2.x, acc[mt][nt][3] + b2.y};
            *(float2*)(g_patch + (size_t)m_a * DD + nn)       = o0;
            *(float2*)(g_patch + (size_t)(m_a + 8) * DD + nn) = o1;
        }
    }
}

// ---------------------------------------------------------------------------
// FP8 (e4m3) GEMM for far/close: 128x128 tile, BK=128 bytes (k32 per MMA),
// 2-stage cp.async, SW128 swizzle + ldmatrix (16B chunks = fp8 k-fragments),
// mma m16n8k32, fused exp/reduce epilogue. acc = 64*sim (operands scaled x8).
//   MODE 1: far    A=B=g_pn8 batch slice (576, clamp+mask)
//   MODE 2: close  A=g_ln8 (1024), B=g_pn8 (36864), batch-split reduce
// ---------------------------------------------------------------------------
#define NCHUNK8 6

template<int MODE>
__global__ __launch_bounds__(256)
void fp8_mma_kernel() {
    if (MODE == 1 && blockIdx.y > blockIdx.x) return;  // symmetric: lower triangle

    extern __shared__ __align__(1024) unsigned char smem[];
    __shared__ float s_red[8];
    const uint32_t sbase = smem_to_u32(smem);
    const int tid = threadIdx.x, lane = tid & 31, wid = tid >> 5;
    const int warp_m = wid & 3, warp_n = wid >> 2;

    int m0, n0;
    const unsigned char *Ap, *Bp;
    if (MODE == 1) { m0 = blockIdx.x * 128; n0 = blockIdx.y * 128;
                     Ap = g_pn8 + (size_t)blockIdx.z * NP * DD; Bp = Ap; }
    else           { m0 = blockIdx.y * 128; n0 = blockIdx.x * 128; Ap = g_ln8; Bp = g_pn8; }

    // Copy plan: rows of 128 fp8 bytes; 4 x 16B segs per operand per chunk.
    const unsigned char* gA[4];
    const unsigned char* gB[4];
    uint32_t swoff[4];
#pragma unroll
    for (int i = 0; i < 4; ++i) {
        int idx = tid + i * 256;
        int rr = idx >> 3, cc = idx & 7;
        swoff[i] = SWZ((uint32_t)(rr * 128 + cc * 16));
        int ra = m0 + rr, rb = n0 + rr;
        if (MODE == 1) {
            ra = ra < NP - 1 ? ra : NP - 1;
            rb = rb < NP - 1 ? rb : NP - 1;
        }
        gA[i] = Ap + (size_t)ra * DD + cc * 16;
        gB[i] = Bp + (size_t)rb * DD + cc * 16;
    }

#define LOAD_CHUNK8(ch, buf) do {                                       \
        uint32_t _sA = sbase + (uint32_t)(buf) * (2 * TILE_B);          \
        uint32_t _sB = _sA + TILE_B;                                    \
        _Pragma("unroll")                                               \
        for (int i = 0; i < 4; ++i) {                                   \
            cp16(_sA + swoff[i], (const void*)(gA[i] + (ch) * 128));    \
            cp16(_sB + swoff[i], (const void*)(gB[i] + (ch) * 128));    \
        }                                                               \
        CP_COMMIT();                                                    \
    } while (0)

    float acc[2][8][4] = {};

    const int arow = warp_m * 32 + (lane & 15);
    const int ac16 = lane >> 4;
    const int brow = warp_n * 64 + (lane & 7) + ((lane >> 4) << 3);
    const int bc16 = (lane >> 3) & 1;

    LOAD_CHUNK8(0, 0);

    for (int ch = 0; ch < NCHUNK8; ++ch) {
        const int buf = ch & 1;
        if (ch < NCHUNK8 - 1) {
            LOAD_CHUNK8(ch + 1, buf ^ 1);
            asm volatile("cp.async.wait_group 1;");
        } else {
            asm volatile("cp.async.wait_group 0;");
        }
        __syncthreads();

        const uint32_t aT = sbase + (uint32_t)buf * (2 * TILE_B);
        const uint32_t bT = aT + TILE_B;
#pragma unroll
        for (int kk = 0; kk < 4; ++kk) {   // kk covers k = 32 fp8 = two 16B chunks
            uint32_t af[2][4];
#pragma unroll
            for (int mt = 0; mt < 2; ++mt) {
                uint32_t off = (uint32_t)((arow + mt * 16) * 128 + (kk * 2 + ac16) * 16);
                ldsm_x4(af[mt], aT + SWZ(off));
            }
#pragma unroll
            for (int nt = 0; nt < 4; ++nt) {
                uint32_t bf4[4];
                uint32_t off = (uint32_t)((brow + nt * 16) * 128 + (kk * 2 + bc16) * 16);
                ldsm_x4(bf4, bT + SWZ(off));
#pragma unroll
                for (int mt = 0; mt < 2; ++mt) {
                    mma_fp8(acc[mt][nt * 2 + 0], af[mt], bf4[0], bf4[1]);
                    mma_fp8(acc[mt][nt * 2 + 1], af[mt], bf4[2], bf4[3]);
                }
            }
        }
        __syncthreads();
    }
#undef LOAD_CHUNK8

    // ---- fused exp / reduce epilogue (acc = 64 * sim) ----
    const int mrow_lo = warp_m * 32 + (lane >> 2);
    const int ncol0   = warp_n * 64 + (lane & 3) * 2;

    if (MODE == 1) {
        float s = 0.f;
#pragma unroll
        for (int mt = 0; mt < 2; ++mt) {
#pragma unroll
            for (int nt = 0; nt < 8; ++nt) {
                int m_a = m0 + mrow_lo + mt * 16;
                int m_b = m_a + 8;
                int nn  = n0 + ncol0 + nt * 8;
                bool nv0 = nn < NP, nv1 = (nn + 1) < NP;
                if (m_a < NP) {
                    if (nv0 && m_a != nn)     s += __expf(EXP_COEF * acc[mt][nt][0]);
                    if (nv1 && m_a != nn + 1) s += __expf(EXP_COEF * acc[mt][nt][1]);
                }
                if (m_b < NP) {
                    if (nv0 && m_b != nn)     s += __expf(EXP_COEF * acc[mt][nt][2]);
                    if (nv1 && m_b != nn + 1) s += __expf(EXP_COEF * acc[mt][nt][3]);
                }
            }
        }
        if (blockIdx.x > blockIdx.y) s *= 2.0f;   // symmetric off-diagonal tile
        s = warpSum(s);
        if (lane == 0) s_red[wid] = s;
        __syncthreads();
        if (tid == 0) {
            float r = 0.f;
#pragma unroll
            for (int i = 0; i < 8; ++i) r += s_red[i];
            atomicAdd(&g_far[blockIdx.z], r);
        }
    } else {
        const int bA    = n0 / NP;                // first batch in this n tile
        const int split = (bA + 1) * NP;
        float s0 = 0.f, s1 = 0.f;
#pragma unroll
        for (int mt = 0; mt < 2; ++mt) {
#pragma unroll
            for (int nt = 0; nt < 8; ++nt) {
                int nn = n0 + ncol0 + nt * 8;     // all 4 regs share this n pair
                float e = __expf(EXP_COEF * acc[mt][nt][0]) + __expf(EXP_COEF * acc[mt][nt][1])
                        + __expf(EXP_COEF * acc[mt][nt][2]) + __expf(EXP_COEF * acc[mt][nt][3]);
                if (nn < split) s0 += e; else s1 += e;
            }
        }
        float r0 = warpSum(s0), r1 = warpSum(s1);
        if (lane == 0) s_red[wid] = r0;
        __syncthreads();
        if (tid == 0) {
            float r = 0.f;
#pragma unroll
            for (int i = 0; i < 8; ++i) r += s_red[i];
            atomicAdd(&g_close[bA], r);
        }
        __syncthreads();
        if (lane == 0) s_red[wid] = r1;
        __syncthreads();
        if (tid == 0 && bA + 1 < BD) {
            float r = 0.f;
#pragma unroll
            for (int i = 0; i < 8; ++i) r += s_red[i];
            if (r != 0.f) atomicAdd(&g_close[bA + 1], r);
        }
    }
}

// ---------------------------------------------------------------------------
// Small kernels
// ---------------------------------------------------------------------------
__global__ void zero_kernel() {
    const int t = threadIdx.x;
    if (t < BD) { g_far[t] = 0.f; g_close[t] = 0.f; }
}

__global__ void finalize_kernel(float* out) {
    const int t = threadIdx.x;  // 64 threads
    float v = logf(g_far[t]) - logf(g_close[t]);
    __shared__ float red[2];
    float s = warpSum(v);
    if ((t & 31) == 0) red[t >> 5] = s;
    __syncthreads();
    if (t == 0) out[0] = (red[0] + red[1]) * (1.0f / (float)BD);
}

// ---------------------------------------------------------------------------
// Launch. Inputs (metadata order): x, conv_w, conv_b, latent. Output: 1 fp32.
// ---------------------------------------------------------------------------
extern "C" void kernel_launch(void* const* d_in, const int* in_sizes, int n_in,
                              void* d_out, int out_size) {
    (void)in_sizes; (void)n_in; (void)out_size;
    const float* x      = (const float*)d_in[0];
    const float* conv_w = (const float*)d_in[1];
    const float* conv_b = (const float*)d_in[2];
    const float* latent = (const float*)d_in[3];
    float* out = (float*)d_out;

    cudaFuncSetAttribute(conv_mma_kernel,  cudaFuncAttributeMaxDynamicSharedMemorySize, SMEM_DYN);
    cudaFuncSetAttribute(fp8_mma_kernel<1>, cudaFuncAttributeMaxDynamicSharedMemorySize, SMEM_DYN);
    cudaFuncSetAttribute(fp8_mma_kernel<2>, cudaFuncAttributeMaxDynamicSharedMemorySize, SMEM_DYN);

    zero_kernel<<<1, 64>>>();
    wconv_kernel<<<576, 256>>>(conv_w);                         // weights -> bf16
    im2col_kernel<<<6912, 256>>>(x);                            // x -> g_xim bf16
    conv_mma_kernel<<<dim3(288, 6), 256, SMEM_DYN>>>(conv_b);   // conv GEMM -> g_patch
    norm_patch_kernel<<<MROWS, 256>>>();                        // -> g_pn8 (e4m3 * 8)
    norm_latent_kernel<<<LL, 256>>>(latent);                    // -> g_ln8 (e4m3 * 8)
    fp8_mma_kernel<1><<<dim3(5, 5, BD), 256, SMEM_DYN>>>();     // far (symmetric)
    fp8_mma_kernel<2><<<dim3(288, 8), 256, SMEM_DYN>>>();       // close
    finalize_kernel<<<1, 64>>>(out);
}

// round 11
// speedup vs baseline: 1.0970x; 1.0970x over previous
#include <cuda_runtime.h>
#include <cuda_bf16.h>
#include <cstdint>
#include <math.h>

// Problem constants
#define BD 64                 // batch
#define NP 576                // patches per image (24*24)
#define DD 768                // hidden = 3*16*16
#define LL 1024               // latents
#define MROWS (BD * NP)       // 36864 flattened (b, patch) rows

// ---------------------------------------------------------------------------
// Scratch (__device__ globals: allocation-free per harness rules)
// ---------------------------------------------------------------------------
__device__ __align__(16) __nv_bfloat16 g_patchb[(size_t)MROWS * DD]; // conv out bf16
__device__ __align__(16) __nv_bfloat16 g_xim [(size_t)MROWS * DD];   // im2col(x) bf16
__device__ __align__(16) __nv_bfloat16 g_pnb [(size_t)MROWS * DD];   // normalized patches bf16
__device__ __align__(16) __nv_bfloat16 g_lnb [(size_t)LL * DD];      // normalized latent bf16
__device__ __align__(16) __nv_bfloat16 g_wb  [(size_t)DD * DD];      // conv weights bf16
__device__ float g_far[BD];
__device__ float g_close[BD];

// ---------------------------------------------------------------------------
// Helpers
// ---------------------------------------------------------------------------
__device__ __forceinline__ uint32_t smem_to_u32(const void* smem_ptr) {
    uint32_t addr;
    asm("{ .reg .u64 tmp; cvta.to.shared.u64 tmp, %1; cvt.u32.u64 %0, tmp; }"
        : "=r"(addr) : "l"(smem_ptr));
    return addr;
}

__device__ __forceinline__ float warpSum(float v) {
#pragma unroll
    for (int o = 16; o; o >>= 1) v += __shfl_xor_sync(0xffffffffu, v, o);
    return v;
}

__device__ __forceinline__ void ldsm_x4(uint32_t* d, uint32_t addr) {
    asm volatile("ldmatrix.sync.aligned.m8n8.x4.shared.b16 {%0,%1,%2,%3}, [%4];"
                 : "=r"(d[0]), "=r"(d[1]), "=r"(d[2]), "=r"(d[3]) : "r"(addr));
}

__device__ __forceinline__ void mma_bf16(float* c, const uint32_t* a,
                                         uint32_t b0, uint32_t b1) {
    asm volatile(
        "mma.sync.aligned.m16n8k16.row.col.f32.bf16.bf16.f32 "
        "{%0,%1,%2,%3}, {%4,%5,%6,%7}, {%8,%9}, {%0,%1,%2,%3};"
        : "+f"(c[0]), "+f"(c[1]), "+f"(c[2]), "+f"(c[3])
        : "r"(a[0]), "r"(a[1]), "r"(a[2]), "r"(a[3]), "r"(b0), "r"(b1));
}

__device__ __forceinline__ void cp16(uint32_t saddr, const void* gptr) {
    asm volatile("cp.async.cg.shared.global [%0], [%1], 16;" :: "r"(saddr), "l"(gptr));
}

#define CP_COMMIT() asm volatile("cp.async.commit_group;")

#define SWZ(off) ((off) ^ (((off) >> 3) & 0x70))

// ---------------------------------------------------------------------------
// Pre-pass kernels: bf16 conversions
// ---------------------------------------------------------------------------

// im2col + fp32->bf16: g_xim[(b*576+np)*768 + k], k = c*256 + rr*16 + cc
__global__ __launch_bounds__(256) void im2col_kernel(const float* __restrict__ x) {
    int s = blockIdx.x * 256 + threadIdx.x;
    int row = s / 48;
    int seg = s - row * 48;
    int b   = row / NP;
    int np  = row - b * NP;
    int ph  = np / 24, pw = np - ph * 24;
    int c   = seg >> 4, rr = seg & 15;
    const float4* src = (const float4*)(x + ((size_t)(b * 3 + c) * 384 + ph * 16 + rr) * 384 + pw * 16);
    float4 q0 = src[0], q1 = src[1], q2 = src[2], q3 = src[3];
    __align__(16) __nv_bfloat162 h[8];
    h[0] = __floats2bfloat162_rn(q0.x, q0.y); h[1] = __floats2bfloat162_rn(q0.z, q0.w);
    h[2] = __floats2bfloat162_rn(q1.x, q1.y); h[3] = __floats2bfloat162_rn(q1.z, q1.w);
    h[4] = __floats2bfloat162_rn(q2.x, q2.y); h[5] = __floats2bfloat162_rn(q2.z, q2.w);
    h[6] = __floats2bfloat162_rn(q3.x, q3.y); h[7] = __floats2bfloat162_rn(q3.z, q3.w);
    uint4* dst = (uint4*)(g_xim + (size_t)row * DD + seg * 16);
    dst[0] = ((const uint4*)h)[0];
    dst[1] = ((const uint4*)h)[1];
}

// conv weights fp32 -> bf16 (OIHW flattening == k order)
__global__ __launch_bounds__(256) void wconv_kernel(const float* __restrict__ w) {
    int i = blockIdx.x * 256 + threadIdx.x;   // 147456 float4s
    float4 q = ((const float4*)w)[i];
    __align__(8) __nv_bfloat162 h2[2] = {__floats2bfloat162_rn(q.x, q.y),
                                         __floats2bfloat162_rn(q.z, q.w)};
    ((uint2*)g_wb)[i] = *(const uint2*)h2;
}

// L2-normalize conv output rows (bf16 in, bf16 out). grid = MROWS, 256 thr.
__global__ __launch_bounds__(256) void norm_patch_kernel() {
    const __nv_bfloat16* p = g_patchb + (size_t)blockIdx.x * DD;
    __nv_bfloat16* o = g_pnb + (size_t)blockIdx.x * DD;
    const int tid = threadIdx.x;
    float v0 = __bfloat162float(p[tid]);
    float v1 = __bfloat162float(p[tid + 256]);
    float v2 = __bfloat162float(p[tid + 512]);
    float ss = v0 * v0 + v1 * v1 + v2 * v2;

    __shared__ float red[8];
    __shared__ float s_inv;
    float t = warpSum(ss);
    if ((tid & 31) == 0) red[tid >> 5] = t;
    __syncthreads();
    if (tid < 32) {
        float u = (tid < 8) ? red[tid] : 0.f;
        u = warpSum(u);
        if (tid == 0) s_inv = 1.0f / fmaxf(sqrtf(u), 1e-8f);
    }
    __syncthreads();
    const float inv = s_inv;
    o[tid]       = __float2bfloat16(v0 * inv);
    o[tid + 256] = __float2bfloat16(v1 * inv);
    o[tid + 512] = __float2bfloat16(v2 * inv);
}

// Normalize latent rows (fp32 in, bf16 out). grid = LL, 256 thr.
__global__ __launch_bounds__(256) void norm_latent_kernel(const float* __restrict__ latent) {
    const float* s = latent + (size_t)blockIdx.x * DD;
    __nv_bfloat16* d = g_lnb + (size_t)blockIdx.x * DD;
    const int tid = threadIdx.x;
    float v0 = s[tid], v1 = s[tid + 256], v2 = s[tid + 512];
    float ss = v0 * v0 + v1 * v1 + v2 * v2;

    __shared__ float red[8];
    __shared__ float s_inv;
    float t = warpSum(ss);
    if ((tid & 31) == 0) red[tid >> 5] = t;
    __syncthreads();
    if (tid < 32) {
        float u = (tid < 8) ? red[tid] : 0.f;
        u = warpSum(u);
        if (tid == 0) s_inv = 1.0f / fmaxf(sqrtf(u), 1e-8f);
    }
    __syncthreads();
    const float inv = s_inv;
    d[tid]       = __float2bfloat16(v0 * inv);
    d[tid + 256] = __float2bfloat16(v1 * inv);
    d[tid + 512] = __float2bfloat16(v2 * inv);
}

// ---------------------------------------------------------------------------
// bf16 HMMA GEMM: 128x128 block tile, BK=64, 2-stage cp.async double buffer,
// SW128-swizzled smem + ldmatrix, mma.sync m16n8k16, fused epilogue.
//   MODE 0: conv   A=g_xim (36864), B=g_wb (768)   -> g_patchb (bf16) + bias
//   MODE 1: far    A=B=g_pnb batch slice (576, clamp+mask) -> exp+reduce
//   MODE 2: close  A=g_lnb (1024),  B=g_pnb (36864) -> exp+reduce (batch split)
// Warp layout: 8 warps = 4 (m) x 2 (n); warp tile 32(m) x 64(n).
// ---------------------------------------------------------------------------
#define NCHUNK 12
#define TILE_B 16384
#define SMEM_DYN (4 * TILE_B)

template<int MODE>
__global__ __launch_bounds__(256)
void mma_kernel(const float* __restrict__ bias) {
    if (MODE == 1 && blockIdx.y > blockIdx.x) return;  // symmetric: lower triangle

    extern __shared__ __align__(1024) unsigned char smem[];
    __shared__ float s_red[8];
    const uint32_t sbase = smem_to_u32(smem);
    const int tid = threadIdx.x, lane = tid & 31, wid = tid >> 5;
    const int warp_m = wid & 3, warp_n = wid >> 2;

    int m0, n0;
    const __nv_bfloat16 *Ap, *Bp;
    if (MODE == 0)      { m0 = blockIdx.x * 128; n0 = blockIdx.y * 128; Ap = g_xim; Bp = g_wb; }
    else if (MODE == 1) { m0 = blockIdx.x * 128; n0 = blockIdx.y * 128;
                          Ap = g_pnb + (size_t)blockIdx.z * NP * DD; Bp = Ap; }
    else                { m0 = blockIdx.y * 128; n0 = blockIdx.x * 128; Ap = g_lnb; Bp = g_pnb; }

    // Per-thread copy plan: 4 x 16B segments for each of A, B per chunk.
    const __nv_bfloat16* gA[4];
    const __nv_bfloat16* gB[4];
    uint32_t swoff[4];
#pragma unroll
    for (int i = 0; i < 4; ++i) {
        int idx = tid + i * 256;
        int rr = idx >> 3, cc = idx & 7;
        uint32_t off = (uint32_t)(rr * 128 + cc * 16);
        swoff[i] = SWZ(off);
        int ra = m0 + rr, rb = n0 + rr;
        if (MODE == 1) {                        // clamp padded rows; masked later
            ra = ra < NP - 1 ? ra : NP - 1;
            rb = rb < NP - 1 ? rb : NP - 1;
        }
        gA[i] = Ap + (size_t)ra * DD + cc * 8;
        gB[i] = Bp + (size_t)rb * DD + cc * 8;
    }

#define LOAD_CHUNK(ch, buf) do {                                        \
        uint32_t _sA = sbase + (uint32_t)(buf) * (2 * TILE_B);          \
        uint32_t _sB = _sA + TILE_B;                                    \
        _Pragma("unroll")                                               \
        for (int i = 0; i < 4; ++i) {                                   \
            cp16(_sA + swoff[i], (const void*)(gA[i] + (ch) * 64));     \
            cp16(_sB + swoff[i], (const void*)(gB[i] + (ch) * 64));     \
        }                                                               \
        CP_COMMIT();                                                    \
    } while (0)

    float acc[2][8][4] = {};

    // ldmatrix lane mappings
    const int arow = warp_m * 32 + (lane & 15);       // + mt*16
    const int ac16 = lane >> 4;                       // k 16B sub-chunk
    const int brow = warp_n * 64 + (lane & 7) + ((lane >> 4) << 3);  // + nt*16
    const int bc16 = (lane >> 3) & 1;

    LOAD_CHUNK(0, 0);

    for (int ch = 0; ch < NCHUNK; ++ch) {
        const int buf = ch & 1;
        if (ch < NCHUNK - 1) {
            LOAD_CHUNK(ch + 1, buf ^ 1);
            asm volatile("cp.async.wait_group 1;");
        } else {
            asm volatile("cp.async.wait_group 0;");
        }
        __syncthreads();

        const uint32_t aT = sbase + (uint32_t)buf * (2 * TILE_B);
        const uint32_t bT = aT + TILE_B;
#pragma unroll
        for (int kk = 0; kk < 4; ++kk) {
            uint32_t af[2][4];
#pragma unroll
            for (int mt = 0; mt < 2; ++mt) {
                uint32_t off = (uint32_t)((arow + mt * 16) * 128 + (kk * 2 + ac16) * 16);
                ldsm_x4(af[mt], aT + SWZ(off));
            }
#pragma unroll
            for (int nt = 0; nt < 4; ++nt) {
                uint32_t bf4[4];
                uint32_t off = (uint32_t)((brow + nt * 16) * 128 + (kk * 2 + bc16) * 16);
                ldsm_x4(bf4, bT + SWZ(off));
#pragma unroll
                for (int mt = 0; mt < 2; ++mt) {
                    mma_bf16(acc[mt][nt * 2 + 0], af[mt], bf4[0], bf4[1]);
                    mma_bf16(acc[mt][nt * 2 + 1], af[mt], bf4[2], bf4[3]);
                }
            }
        }
        __syncthreads();   // protect buf before chunk ch+2 overwrites it
    }

    // ---- epilogue ----
    const int mrow_lo = warp_m * 32 + (lane >> 2);   // + mt*16 ; +8 for hi half
    const int ncol0   = warp_n * 64 + (lane & 3) * 2;

    if (MODE == 0) {
#pragma unroll
        for (int mt = 0; mt < 2; ++mt) {
#pragma unroll
            for (int nt = 0; nt < 8; ++nt) {
                int m_a = m0 + mrow_lo + mt * 16;
                int nn  = n0 + ncol0 + nt * 8;
                float2 b2 = *(const float2*)(bias + nn);
                __nv_bfloat162 o0 = __floats2bfloat162_rn(acc[mt][nt][0] + b2.x,
                                                          acc[mt][nt][1] + b2.y);
                __nv_bfloat162 o1 = __floats2bfloat162_rn(acc[mt][nt][2] + b2.x,
                                                          acc[mt][nt][3] + b2.y);
                *(__nv_bfloat162*)(g_patchb + (size_t)m_a * DD + nn)       = o0;
                *(__nv_bfloat162*)(g_patchb + (size_t)(m_a + 8) * DD + nn) = o1;
            }
        }
    } else if (MODE == 1) {
        float s = 0.f;
#pragma unroll
        for (int mt = 0; mt < 2; ++mt) {
#pragma unroll
            for (int nt = 0; nt < 8; ++nt) {
                int m_a = m0 + mrow_lo + mt * 16;
                int m_b = m_a + 8;
                int nn  = n0 + ncol0 + nt * 8;
                bool nv0 = nn < NP, nv1 = (nn + 1) < NP;
                if (m_a < NP) {
                    if (nv0 && m_a != nn)     s += __expf(2.0f * acc[mt][nt][0]);
                    if (nv1 && m_a != nn + 1) s += __expf(2.0f * acc[mt][nt][1]);
                }
                if (m_b < NP) {
                    if (nv0 && m_b != nn)     s += __expf(2.0f * acc[mt][nt][2]);
                    if (nv1 && m_b != nn + 1) s += __expf(2.0f * acc[mt][nt][3]);
                }
            }
        }
        if (blockIdx.x > blockIdx.y) s *= 2.0f;   // symmetric off-diagonal tile
        s = warpSum(s);
        if (lane == 0) s_red[wid] = s;
        __syncthreads();
        if (tid == 0) {
            float r = 0.f;
#pragma unroll
            for (int i = 0; i < 8; ++i) r += s_red[i];
            atomicAdd(&g_far[blockIdx.z], r);
        }
    } else {
        const int bA    = n0 / NP;                // first batch in this n tile
        const int split = (bA + 1) * NP;
        float s0 = 0.f, s1 = 0.f;
#pragma unroll
        for (int mt = 0; mt < 2; ++mt) {
#pragma unroll
            for (int nt = 0; nt < 8; ++nt) {
                int nn = n0 + ncol0 + nt * 8;     // all 4 regs share this n pair
                float e = __expf(2.0f * acc[mt][nt][0]) + __expf(2.0f * acc[mt][nt][1])
                        + __expf(2.0f * acc[mt][nt][2]) + __expf(2.0f * acc[mt][nt][3]);
                if (nn < split) s0 += e; else s1 += e;
            }
        }
        float r0 = warpSum(s0), r1 = warpSum(s1);
        if (lane == 0) s_red[wid] = r0;
        __syncthreads();
        if (tid == 0) {
            float r = 0.f;
#pragma unroll
            for (int i = 0; i < 8; ++i) r += s_red[i];
            atomicAdd(&g_close[bA], r);
        }
        __syncthreads();
        if (lane == 0) s_red[wid] = r1;
        __syncthreads();
        if (tid == 0 && bA + 1 < BD) {
            float r = 0.f;
#pragma unroll
            for (int i = 0; i < 8; ++i) r += s_red[i];
            if (r != 0.f) atomicAdd(&g_close[bA + 1], r);
        }
    }
#undef LOAD_CHUNK
}

// ---------------------------------------------------------------------------
// Small kernels
// ---------------------------------------------------------------------------
__global__ void zero_kernel() {
    const int t = threadIdx.x;
    if (t < BD) { g_far[t] = 0.f; g_close[t] = 0.f; }
}

__global__ void finalize_kernel(float* out) {
    const int t = threadIdx.x;  // 64 threads
    float v = logf(g_far[t]) - logf(g_close[t]);
    __shared__ float red[2];
    float s = warpSum(v);
    if ((t & 31) == 0) red[t >> 5] = s;
    __syncthreads();
    if (t == 0) out[0] = (red[0] + red[1]) * (1.0f / (float)BD);
}

// ---------------------------------------------------------------------------
// Launch. Inputs (metadata order): x, conv_w, conv_b, latent. Output: 1 fp32.
// ---------------------------------------------------------------------------
extern "C" void kernel_launch(void* const* d_in, const int* in_sizes, int n_in,
                              void* d_out, int out_size) {
    (void)in_sizes; (void)n_in; (void)out_size;
    const float* x      = (const float*)d_in[0];
    const float* conv_w = (const float*)d_in[1];
    const float* conv_b = (const float*)d_in[2];
    const float* latent = (const float*)d_in[3];
    float* out = (float*)d_out;

    cudaFuncSetAttribute(mma_kernel<0>, cudaFuncAttributeMaxDynamicSharedMemorySize, SMEM_DYN);
    cudaFuncSetAttribute(mma_kernel<1>, cudaFuncAttributeMaxDynamicSharedMemorySize, SMEM_DYN);
    cudaFuncSetAttribute(mma_kernel<2>, cudaFuncAttributeMaxDynamicSharedMemorySize, SMEM_DYN);

    zero_kernel<<<1, 64>>>();
    wconv_kernel<<<576, 256>>>(conv_w);                       // weights -> bf16
    im2col_kernel<<<6912, 256>>>(x);                          // x -> g_xim bf16
    mma_kernel<0><<<dim3(288, 6), 256, SMEM_DYN>>>(conv_b);   // conv GEMM -> g_patchb
    norm_patch_kernel<<<MROWS, 256>>>();                      // -> g_pnb bf16
    norm_latent_kernel<<<LL, 256>>>(latent);                  // -> g_lnb bf16
    mma_kernel<1><<<dim3(5, 5, BD), 256, SMEM_DYN>>>(nullptr);   // far (symmetric)
    mma_kernel<2><<<dim3(288, 8), 256, SMEM_DYN>>>(nullptr);     // close
    finalize_kernel<<<1, 64>>>(out);
}